// round 14
// baseline (speedup 1.0000x reference)
#include <cuda_runtime.h>
#include <cuda_fp16.h>
#include <cstdint>

#define N_NODES   100000
#define N_EDGES   1600000
#define VOCAB     128
#define D         30
#define N_CLASSES 5
#define NB_PRE    147                // preproc grid: < 148 SMs => all resident
#define NB_SCAN   98                 // scan sub-phase blocks (98*1024 >= N_NODES)
#define FLAGBIT   0x40000000
#define NPB       64                 // nodes per block in layer kernels
#define SROW_CAP  (N_EDGES + 3 * N_NODES + 64)

// Scratch (device globals; float4 => 16B alignment for LDG.128)
__device__ float4 g_hsA[(N_NODES + 1) * 4];     // +1: reserved zero row
__device__ float4 g_hsB[(N_NODES + 1) * 4];
__device__ float  g_inv[N_NODES];
__device__ int    g_pre[2 * N_NODES + 160];     // cnt | degr | state(128) | bars(32)
__device__ int    g_off[N_NODES + 1];           // padded CSR offsets (multiples of 4)
__device__ int    g_cur[N_NODES];
__device__ int    g_srow[SROW_CAP];

__device__ __forceinline__ __half2 H2(float f) { return *(const __half2*)&f; }

// Device-wide barrier (safe: all NB_PRE blocks resident). ctr zeroed by memset.
__device__ __forceinline__ void gbar(int* ctr) {
    __syncthreads();
    __threadfence();
    if (threadIdx.x == 0) {
        atomicAdd(ctr, 1);
        while (*(volatile int*)ctr < NB_PRE) { }
    }
    __syncthreads();
}

// ---------------------------------------------------------------------------
// One-kernel preprocessing: hist -> scan(+inv,+hs0,+pad) -> scatter.
__global__ void __launch_bounds__(256)
k_preproc(const int* __restrict__ row, const int* __restrict__ col,
          const int* __restrict__ x, const float* __restrict__ emb,
          int* __restrict__ off, int* __restrict__ cur,
          float* __restrict__ inv, __half2* __restrict__ hs0,
          int* __restrict__ state, int* __restrict__ srow,
          int* __restrict__ cnt, int* __restrict__ degr,
          int* __restrict__ bars) {
    int t = threadIdx.x, bid = blockIdx.x;
    int gtid = bid * 256 + t;
    const int GSTRIDE = NB_PRE * 256;

    // ---- Phase A: degree histograms (cnt/degr zeroed by memset) ----
    #pragma unroll 4
    for (int e = gtid; e < N_EDGES; e += GSTRIDE) {
        atomicAdd(&cnt[col[e]], 1);
        atomicAdd(&degr[row[e]], 1);
    }
    gbar(bars + 0);

    // ---- Phase B: single-pass scan over padded counts (blocks < NB_SCAN) ----
    if (bid < NB_SCAN) {
        __shared__ int wsum[8];
        __shared__ int sPrefix;
        int lane = t & 31, wid = t >> 5;
        int base = bid * 1024 + t * 4;

        int v[4], p[4];
        #pragma unroll
        for (int j = 0; j < 4; j++) {
            int i = base + j;
            v[j] = (i < N_NODES) ? cnt[i] : 0;
            p[j] = (v[j] + 3) & ~3;           // padded to multiple of 4
        }
        int tsum = p[0] + p[1] + p[2] + p[3];

        int inc = tsum;
        #pragma unroll
        for (int d = 1; d < 32; d <<= 1) {
            int u = __shfl_up_sync(~0u, inc, d);
            if (lane >= d) inc += u;
        }
        if (lane == 31) wsum[wid] = inc;
        __syncthreads();
        if (wid == 0) {
            int w = (lane < 8) ? wsum[lane] : 0;
            #pragma unroll
            for (int d = 1; d < 8; d <<= 1) {
                int u = __shfl_up_sync(~0u, w, d);
                if (lane >= d) w += u;
            }
            if (lane < 8) wsum[lane] = w;
        }
        __syncthreads();
        int warpBase = (wid == 0) ? 0 : wsum[wid - 1];
        int texcl = warpBase + inc - tsum;
        int blockAgg = wsum[7];
        __syncthreads();

        if (t == 0) atomicExch(&state[bid], blockAgg | FLAGBIT);

        int pref = 0;
        if (t < bid) {
            int s;
            do { s = atomicOr(&state[t], 0); } while (!(s & FLAGBIT));
            pref = s & ~FLAGBIT;
        }
        #pragma unroll
        for (int d = 16; d > 0; d >>= 1) pref += __shfl_down_sync(~0u, pref, d);
        if (lane == 0) wsum[wid] = pref;
        __syncthreads();
        if (t == 0) {
            int pp = 0;
            #pragma unroll
            for (int j = 0; j < 8; j++) pp += wsum[j];
            sPrefix = pp;
        }
        __syncthreads();

        int e = sPrefix + texcl;
        #pragma unroll
        for (int j = 0; j < 4; j++) {
            int i = base + j;
            if (i < N_NODES) {
                off[i] = e;
                cur[i] = e;
                for (int q = v[j]; q < p[j]; q++) srow[e + q] = N_NODES; // pad
                float iv = 1.0f / (1.0f + (float)degr[i]);  // +1 = self loop
                inv[i] = iv;
                // hs0[i] = fp16(emb[x[i]] * iv), built in regs, 4x STG.128
                const float* er = emb + x[i] * D;
                float4 fr[4];
                __half2* hp = reinterpret_cast<__half2*>(fr);
                #pragma unroll
                for (int d = 0; d < 15; d++)
                    hp[d] = __floats2half2_rn(er[2 * d] * iv, er[2 * d + 1] * iv);
                hp[15] = __floats2half2_rn(0.0f, 0.0f);
                float4* dst = reinterpret_cast<float4*>(hs0 + i * 16);
                dst[0] = fr[0]; dst[1] = fr[1]; dst[2] = fr[2]; dst[3] = fr[3];
                if (i == N_NODES - 1) off[N_NODES] = e + p[j];
            }
            e += p[j];
        }
        // reserved zero feature row
        if (bid == 0 && t < 16) hs0[N_NODES * 16 + t] = __floats2half2_rn(0.0f, 0.0f);
    }
    gbar(bars + 1);

    // ---- Phase C: counting-sort scatter ----
    #pragma unroll 4
    for (int e = gtid; e < N_EDGES; e += GSTRIDE) {
        int p = atomicAdd(&cur[col[e]], 1);
        srow[p] = row[e];
    }
}

// ---------------------------------------------------------------------------
// Fused layer (R10 shape — no occupancy cap, ~37-40 regs, NO spills).
// Phase 1: 4 lanes/node, int4 srow load + 4x LDG.128 feature rows; fp32
// accumulate; padded CSR => no tail. Phase 2: matmul + relu epilogue;
// FINAL emits 5-class logits.
template <bool FINAL>
__global__ void __launch_bounds__(256)
k_layer(const int* __restrict__ off, const int* __restrict__ srow,
        const float4* __restrict__ hs,
        const float* __restrict__ W, const float* __restrict__ b,
        const float* __restrict__ inv,
        __half2* __restrict__ hs_out,
        const float* __restrict__ Wout, const float* __restrict__ bout,
        float* __restrict__ out) {
    __shared__ float  sAgg[NPB][33];
    __shared__ float2 Wt2[D * 16];     // Wt2[k*16+l] = (W[2l][k], W[2l+1][k])
    __shared__ float2 b2s[16];
    __shared__ float  Wo[N_CLASSES * D];
    __shared__ float  bo[N_CLASSES];

    int tid = threadIdx.x;
    if (!FINAL && blockIdx.x == 0 && tid < 16)   // keep zero row zero
        hs_out[N_NODES * 16 + tid] = __floats2half2_rn(0.0f, 0.0f);

    for (int i = tid; i < D * 16; i += 256) {
        int l = i & 15, k = i >> 4;
        float w0 = (2 * l     < D) ? W[(2 * l)     * D + k] : 0.0f;
        float w1 = (2 * l + 1 < D) ? W[(2 * l + 1) * D + k] : 0.0f;
        Wt2[i] = make_float2(w0, w1);
    }
    if (tid < 16) {
        int l = tid;
        b2s[l] = make_float2((2 * l < D) ? b[2 * l] : 0.0f,
                             (2 * l + 1 < D) ? b[2 * l + 1] : 0.0f);
    }
    if (FINAL) {
        if (tid < N_CLASSES * D) Wo[tid] = Wout[tid];
        if (tid < N_CLASSES)     bo[tid] = bout[tid];
    }

    // ---- Phase 1: aggregation (4 lanes per node) ----
    {
        int g = tid >> 2, lane = tid & 3;
        int n = blockIdx.x * NPB + g;
        if (n >= N_NODES) n = N_NODES - 1;           // benign duplicates

        int beg = __ldg(off + n), end = __ldg(off + n + 1);  // multiple of 4
        float4 sv = __ldg(hs + (n << 2) + lane);             // self loop
        float2 a0 = __half22float2(H2(sv.x));
        float2 a1 = __half22float2(H2(sv.y));
        float2 a2 = __half22float2(H2(sv.z));
        float2 a3 = __half22float2(H2(sv.w));

        for (int i = beg; i < end; i += 4) {
            int4 s4 = __ldg(reinterpret_cast<const int4*>(srow + i));
            float4 v0 = __ldg(hs + (s4.x << 2) + lane);
            float4 v1 = __ldg(hs + (s4.y << 2) + lane);
            float4 v2 = __ldg(hs + (s4.z << 2) + lane);
            float4 v3 = __ldg(hs + (s4.w << 2) + lane);
            float2 u;
            u = __half22float2(H2(v0.x)); a0.x += u.x; a0.y += u.y;
            u = __half22float2(H2(v0.y)); a1.x += u.x; a1.y += u.y;
            u = __half22float2(H2(v0.z)); a2.x += u.x; a2.y += u.y;
            u = __half22float2(H2(v0.w)); a3.x += u.x; a3.y += u.y;
            u = __half22float2(H2(v1.x)); a0.x += u.x; a0.y += u.y;
            u = __half22float2(H2(v1.y)); a1.x += u.x; a1.y += u.y;
            u = __half22float2(H2(v1.z)); a2.x += u.x; a2.y += u.y;
            u = __half22float2(H2(v1.w)); a3.x += u.x; a3.y += u.y;
            u = __half22float2(H2(v2.x)); a0.x += u.x; a0.y += u.y;
            u = __half22float2(H2(v2.y)); a1.x += u.x; a1.y += u.y;
            u = __half22float2(H2(v2.z)); a2.x += u.x; a2.y += u.y;
            u = __half22float2(H2(v2.w)); a3.x += u.x; a3.y += u.y;
            u = __half22float2(H2(v3.x)); a0.x += u.x; a0.y += u.y;
            u = __half22float2(H2(v3.y)); a1.x += u.x; a1.y += u.y;
            u = __half22float2(H2(v3.z)); a2.x += u.x; a2.y += u.y;
            u = __half22float2(H2(v3.w)); a3.x += u.x; a3.y += u.y;
        }
        float* rw = &sAgg[g][lane * 8];
        rw[0] = a0.x; rw[1] = a0.y; rw[2] = a1.x; rw[3] = a1.y;
        rw[4] = a2.x; rw[5] = a2.y; rw[6] = a3.x; rw[7] = a3.y;
    }
    __syncthreads();

    // ---- Phase 2: matmul + relu (+ final projection), 16 lanes/node ----
    int l = tid & 15, g2 = tid >> 4;
    #pragma unroll
    for (int p = 0; p < 4; p++) {
        int gl = p * 16 + g2;
        int n = blockIdx.x * NPB + gl;
        if (n >= N_NODES) n = N_NODES - 1;           // benign duplicates

        float2 o = b2s[l];
        #pragma unroll
        for (int k = 0; k < D; k++) {
            float av = sAgg[gl][k];
            float2 w = Wt2[(k << 4) + l];
            o.x = fmaf(av, w.x, o.x);
            o.y = fmaf(av, w.y, o.y);
        }
        o.x = fmaxf(o.x, 0.0f);
        o.y = fmaxf(o.y, 0.0f);
        if (2 * l >= D)     o.x = 0.0f;
        if (2 * l + 1 >= D) o.y = 0.0f;

        if (!FINAL) {
            float iv = inv[n];
            hs_out[(n << 4) + l] = __floats2half2_rn(o.x * iv, o.y * iv);
        } else {
            __syncwarp();
            sAgg[gl][2 * l]     = o.x;
            sAgg[gl][2 * l + 1] = o.y;
            __syncwarp();
            if (l < N_CLASSES) {
                float acc = bo[l];
                #pragma unroll
                for (int k = 0; k < D; k++)
                    acc = fmaf(sAgg[gl][k], Wo[l * D + k], acc);
                out[n * N_CLASSES + l] = acc;
            }
            __syncwarp();
        }
    }
}

// ---------------------------------------------------------------------------
extern "C" void kernel_launch(void* const* d_in, const int* in_sizes, int n_in,
                              void* d_out, int out_size) {
    const int*   x    = (const int*)  d_in[0];
    const int*   ei   = (const int*)  d_in[1];   // [2, E] row-major
    const float* emb  = (const float*)d_in[2];
    const float* W1   = (const float*)d_in[3];
    const float* b1   = (const float*)d_in[4];
    const float* W2   = (const float*)d_in[5];
    const float* b2   = (const float*)d_in[6];
    const float* W3   = (const float*)d_in[7];
    const float* b3   = (const float*)d_in[8];
    const float* Wout = (const float*)d_in[9];
    const float* bout = (const float*)d_in[10];
    float* out = (float*)d_out;

    const int* row = ei;
    const int* col = ei + N_EDGES;

    float4 *hsA, *hsB;
    float *inv;
    int *pre, *off, *cur, *srow;
    cudaGetSymbolAddress((void**)&hsA,  g_hsA);
    cudaGetSymbolAddress((void**)&hsB,  g_hsB);
    cudaGetSymbolAddress((void**)&inv,  g_inv);
    cudaGetSymbolAddress((void**)&pre,  g_pre);
    cudaGetSymbolAddress((void**)&off,  g_off);
    cudaGetSymbolAddress((void**)&cur,  g_cur);
    cudaGetSymbolAddress((void**)&srow, g_srow);

    int* cnt   = pre;
    int* degr  = pre + N_NODES;
    int* state = pre + 2 * N_NODES;
    int* bars  = pre + 2 * N_NODES + 128;

    const int NT = 256;
    const int gLayer = (N_NODES + NPB - 1) / NPB; // 1563

    // 1. zero cnt/degr/state/bars  2. fused hist+scan+scatter  3-5. layers
    cudaMemsetAsync(pre, 0, (2 * N_NODES + 160) * sizeof(int));
    k_preproc<<<NB_PRE, NT>>>(row, col, x, emb, off, cur, inv,
                              (__half2*)hsA, state, srow, cnt, degr, bars);

    k_layer<false><<<gLayer, NT>>>(off, srow, hsA, W1, b1, inv,
                                   (__half2*)hsB, nullptr, nullptr, nullptr);
    k_layer<false><<<gLayer, NT>>>(off, srow, hsB, W2, b2, inv,
                                   (__half2*)hsA, nullptr, nullptr, nullptr);
    k_layer<true> <<<gLayer, NT>>>(off, srow, hsA, W3, b3, inv,
                                   nullptr, Wout, bout, out);
}

// round 15
// speedup vs baseline: 1.6813x; 1.6813x over previous
#include <cuda_runtime.h>
#include <cuda_fp16.h>
#include <cstdint>

#define N_NODES   100000
#define N_EDGES   1600000
#define VOCAB     128
#define D         30
#define N_CLASSES 5
#define SCAN_NB   98                 // 98 * 1024 = 100352 >= N_NODES
#define FLAGBIT   0x40000000
#define NPB       64                 // nodes per block in layer kernels
#define SROW_CAP  (N_EDGES + 3 * N_NODES + 64)

// Scratch (device globals; float4 => 16B alignment for LDG.128)
__device__ float4 g_hsA[(N_NODES + 1) * 4];     // +1: reserved zero row
__device__ float4 g_hsB[(N_NODES + 1) * 4];
__device__ float  g_hout[N_NODES * 32];         // fp32 final-layer hidden
__device__ float  g_inv[N_NODES];
__device__ int    g_pre[2 * N_NODES + 128];     // cnt | degr | state(128)
__device__ int    g_off[N_NODES + 1];           // padded CSR offsets (multiples of 4)
__device__ int    g_cur[N_NODES];
__device__ int    g_srow[SROW_CAP];

__device__ __forceinline__ __half2 H2(float f) { return *(const __half2*)&f; }

// ---------------------------------------------------------------------------
__global__ void k_hist(const int* __restrict__ row, const int* __restrict__ col,
                       int* __restrict__ cnt, int* __restrict__ degr) {
    int e = blockIdx.x * blockDim.x + threadIdx.x;
    if (e < N_EDGES) {
        atomicAdd(&cnt[col[e]], 1);
        atomicAdd(&degr[row[e]], 1);
    }
}

// Single-pass scan over PADDED counts (ceil(cnt/4)*4): off/cur + inv_deg + hs0
// + srow padding fill (pad slots -> zero row N_NODES).
__global__ void __launch_bounds__(256)
k_scan(const int* __restrict__ cnt, const int* __restrict__ degr,
       const int* __restrict__ x, const float* __restrict__ emb,
       int* __restrict__ off, int* __restrict__ cur,
       float* __restrict__ inv, __half2* __restrict__ hs0,
       int* __restrict__ state, int* __restrict__ srow) {
    __shared__ int wsum[8];
    __shared__ int sPrefix;
    int t = threadIdx.x, bid = blockIdx.x;
    int lane = t & 31, wid = t >> 5;
    int base = bid * 1024 + t * 4;

    int v[4], p[4];
    #pragma unroll
    for (int j = 0; j < 4; j++) {
        int i = base + j;
        v[j] = (i < N_NODES) ? cnt[i] : 0;
        p[j] = (v[j] + 3) & ~3;           // padded to multiple of 4
    }
    int tsum = p[0] + p[1] + p[2] + p[3];

    int inc = tsum;
    #pragma unroll
    for (int d = 1; d < 32; d <<= 1) {
        int u = __shfl_up_sync(~0u, inc, d);
        if (lane >= d) inc += u;
    }
    if (lane == 31) wsum[wid] = inc;
    __syncthreads();
    if (wid == 0) {
        int w = (lane < 8) ? wsum[lane] : 0;
        #pragma unroll
        for (int d = 1; d < 8; d <<= 1) {
            int u = __shfl_up_sync(~0u, w, d);
            if (lane >= d) w += u;
        }
        if (lane < 8) wsum[lane] = w;
    }
    __syncthreads();
    int warpBase = (wid == 0) ? 0 : wsum[wid - 1];
    int texcl = warpBase + inc - tsum;
    int blockAgg = wsum[7];
    __syncthreads();

    if (t == 0) atomicExch(&state[bid], blockAgg | FLAGBIT);

    int pref = 0;
    if (t < bid) {
        int s;
        do { s = atomicOr(&state[t], 0); } while (!(s & FLAGBIT));
        pref = s & ~FLAGBIT;
    }
    #pragma unroll
    for (int d = 16; d > 0; d >>= 1) pref += __shfl_down_sync(~0u, pref, d);
    if (lane == 0) wsum[wid] = pref;
    __syncthreads();
    if (t == 0) {
        int pp = 0;
        #pragma unroll
        for (int j = 0; j < 8; j++) pp += wsum[j];
        sPrefix = pp;
    }
    __syncthreads();

    int e = sPrefix + texcl;
    #pragma unroll
    for (int j = 0; j < 4; j++) {
        int i = base + j;
        if (i < N_NODES) {
            off[i] = e;
            cur[i] = e;
            for (int q = v[j]; q < p[j]; q++) srow[e + q] = N_NODES;  // pad -> zero row
            float iv = 1.0f / (1.0f + (float)degr[i]);   // +1 = self loop
            inv[i] = iv;
            const float* er = emb + x[i] * D;
            float4 fr[4];
            __half2* hp = reinterpret_cast<__half2*>(fr);
            #pragma unroll
            for (int d = 0; d < 15; d++)
                hp[d] = __floats2half2_rn(er[2 * d] * iv, er[2 * d + 1] * iv);
            hp[15] = __floats2half2_rn(0.0f, 0.0f);
            float4* dst = reinterpret_cast<float4*>(hs0 + i * 16);
            dst[0] = fr[0]; dst[1] = fr[1]; dst[2] = fr[2]; dst[3] = fr[3];
            if (i == N_NODES - 1) off[N_NODES] = e + p[j];
        }
        e += p[j];
    }
    // reserved zero feature row
    if (bid == 0 && t < 16) hs0[N_NODES * 16 + t] = __floats2half2_rn(0.0f, 0.0f);
}

__global__ void k_scatter(const int* __restrict__ row, const int* __restrict__ col,
                          int* __restrict__ cur, int* __restrict__ srow) {
    int e = blockIdx.x * blockDim.x + threadIdx.x;
    if (e < N_EDGES) {
        int p = atomicAdd(&cur[col[e]], 1);
        srow[p] = row[e];
    }
}

// ---------------------------------------------------------------------------
// Fused layer (R10 shape). Phase 1: 4 lanes/node, int4 srow load + 4x LDG.128
// feature rows; fp32 accumulate; padded CSR => no tail. Phase 2: matmul + relu
// epilogue. FINAL stores fp32 h (no projection, no extra smem, no spills);
// the 5-class projection runs in k_out.
template <bool FINAL>
__global__ void __launch_bounds__(256)
k_layer(const int* __restrict__ off, const int* __restrict__ srow,
        const float4* __restrict__ hs,
        const float* __restrict__ W, const float* __restrict__ b,
        const float* __restrict__ inv,
        __half2* __restrict__ hs_out,
        float* __restrict__ hout) {
    __shared__ float  sAgg[NPB][33];
    __shared__ float2 Wt2[D * 16];     // Wt2[k*16+l] = (W[2l][k], W[2l+1][k])
    __shared__ float2 b2s[16];

    int tid = threadIdx.x;
    if (!FINAL && blockIdx.x == 0 && tid < 16)   // keep zero row zero
        hs_out[N_NODES * 16 + tid] = __floats2half2_rn(0.0f, 0.0f);

    for (int i = tid; i < D * 16; i += 256) {
        int l = i & 15, k = i >> 4;
        float w0 = (2 * l     < D) ? W[(2 * l)     * D + k] : 0.0f;
        float w1 = (2 * l + 1 < D) ? W[(2 * l + 1) * D + k] : 0.0f;
        Wt2[i] = make_float2(w0, w1);
    }
    if (tid < 16) {
        int l = tid;
        b2s[l] = make_float2((2 * l < D) ? b[2 * l] : 0.0f,
                             (2 * l + 1 < D) ? b[2 * l + 1] : 0.0f);
    }

    // ---- Phase 1: aggregation (4 lanes per node) ----
    {
        int g = tid >> 2, lane = tid & 3;
        int n = blockIdx.x * NPB + g;
        if (n >= N_NODES) n = N_NODES - 1;           // benign duplicates

        int beg = __ldg(off + n), end = __ldg(off + n + 1);  // multiple of 4
        float4 sv = __ldg(hs + (n << 2) + lane);             // self loop
        float2 a0 = __half22float2(H2(sv.x));
        float2 a1 = __half22float2(H2(sv.y));
        float2 a2 = __half22float2(H2(sv.z));
        float2 a3 = __half22float2(H2(sv.w));

        for (int i = beg; i < end; i += 4) {
            int4 s4 = __ldg(reinterpret_cast<const int4*>(srow + i));
            float4 v0 = __ldg(hs + (s4.x << 2) + lane);
            float4 v1 = __ldg(hs + (s4.y << 2) + lane);
            float4 v2 = __ldg(hs + (s4.z << 2) + lane);
            float4 v3 = __ldg(hs + (s4.w << 2) + lane);
            float2 u;
            u = __half22float2(H2(v0.x)); a0.x += u.x; a0.y += u.y;
            u = __half22float2(H2(v0.y)); a1.x += u.x; a1.y += u.y;
            u = __half22float2(H2(v0.z)); a2.x += u.x; a2.y += u.y;
            u = __half22float2(H2(v0.w)); a3.x += u.x; a3.y += u.y;
            u = __half22float2(H2(v1.x)); a0.x += u.x; a0.y += u.y;
            u = __half22float2(H2(v1.y)); a1.x += u.x; a1.y += u.y;
            u = __half22float2(H2(v1.z)); a2.x += u.x; a2.y += u.y;
            u = __half22float2(H2(v1.w)); a3.x += u.x; a3.y += u.y;
            u = __half22float2(H2(v2.x)); a0.x += u.x; a0.y += u.y;
            u = __half22float2(H2(v2.y)); a1.x += u.x; a1.y += u.y;
            u = __half22float2(H2(v2.z)); a2.x += u.x; a2.y += u.y;
            u = __half22float2(H2(v2.w)); a3.x += u.x; a3.y += u.y;
            u = __half22float2(H2(v3.x)); a0.x += u.x; a0.y += u.y;
            u = __half22float2(H2(v3.y)); a1.x += u.x; a1.y += u.y;
            u = __half22float2(H2(v3.z)); a2.x += u.x; a2.y += u.y;
            u = __half22float2(H2(v3.w)); a3.x += u.x; a3.y += u.y;
        }
        float* rw = &sAgg[g][lane * 8];
        rw[0] = a0.x; rw[1] = a0.y; rw[2] = a1.x; rw[3] = a1.y;
        rw[4] = a2.x; rw[5] = a2.y; rw[6] = a3.x; rw[7] = a3.y;
    }
    __syncthreads();

    // ---- Phase 2: matmul + relu, 16 lanes/node ----
    int l = tid & 15, g2 = tid >> 4;
    #pragma unroll
    for (int p = 0; p < 4; p++) {
        int gl = p * 16 + g2;
        int n = blockIdx.x * NPB + gl;
        if (n >= N_NODES) n = N_NODES - 1;           // benign duplicates

        float2 o = b2s[l];
        #pragma unroll
        for (int k = 0; k < D; k++) {
            float av = sAgg[gl][k];
            float2 w = Wt2[(k << 4) + l];
            o.x = fmaf(av, w.x, o.x);
            o.y = fmaf(av, w.y, o.y);
        }
        o.x = fmaxf(o.x, 0.0f);
        o.y = fmaxf(o.y, 0.0f);
        if (2 * l >= D)     o.x = 0.0f;
        if (2 * l + 1 >= D) o.y = 0.0f;

        if (!FINAL) {
            float iv = inv[n];
            hs_out[(n << 4) + l] = __floats2half2_rn(o.x * iv, o.y * iv);
        } else {
            hout[(n << 5) + 2 * l]     = o.x;       // fp32, coalesced
            hout[(n << 5) + 2 * l + 1] = o.y;
        }
    }
}

// out[n][j] = sum_k h[n][k] * Wout[j][k] + bout[j], one thread per node.
__global__ void __launch_bounds__(256)
k_out(const float* __restrict__ h, const float* __restrict__ Wout,
      const float* __restrict__ bout, float* __restrict__ out) {
    __shared__ float Ws[N_CLASSES * D];
    __shared__ float bs[N_CLASSES];
    int tid = threadIdx.x;
    if (tid < N_CLASSES * D) Ws[tid] = Wout[tid];
    if (tid < N_CLASSES)     bs[tid] = bout[tid];
    __syncthreads();
    int n = blockIdx.x * blockDim.x + tid;
    if (n >= N_NODES) return;
    float hv[32];
    const float4* hp = reinterpret_cast<const float4*>(h + ((long)n << 5));
    #pragma unroll
    for (int q = 0; q < 8; q++) {
        float4 f = hp[q];
        hv[4*q] = f.x; hv[4*q+1] = f.y; hv[4*q+2] = f.z; hv[4*q+3] = f.w;
    }
    #pragma unroll
    for (int j = 0; j < N_CLASSES; j++) {
        float acc = bs[j];
        #pragma unroll
        for (int k = 0; k < D; k++)
            acc = fmaf(hv[k], Ws[j * D + k], acc);
        out[n * N_CLASSES + j] = acc;
    }
}

// ---------------------------------------------------------------------------
extern "C" void kernel_launch(void* const* d_in, const int* in_sizes, int n_in,
                              void* d_out, int out_size) {
    const int*   x    = (const int*)  d_in[0];
    const int*   ei   = (const int*)  d_in[1];   // [2, E] row-major
    const float* emb  = (const float*)d_in[2];
    const float* W1   = (const float*)d_in[3];
    const float* b1   = (const float*)d_in[4];
    const float* W2   = (const float*)d_in[5];
    const float* b2   = (const float*)d_in[6];
    const float* W3   = (const float*)d_in[7];
    const float* b3   = (const float*)d_in[8];
    const float* Wout = (const float*)d_in[9];
    const float* bout = (const float*)d_in[10];
    float* out = (float*)d_out;

    const int* row = ei;
    const int* col = ei + N_EDGES;

    float4 *hsA, *hsB;
    float *hout, *inv;
    int *pre, *off, *cur, *srow;
    cudaGetSymbolAddress((void**)&hsA,  g_hsA);
    cudaGetSymbolAddress((void**)&hsB,  g_hsB);
    cudaGetSymbolAddress((void**)&hout, g_hout);
    cudaGetSymbolAddress((void**)&inv,  g_inv);
    cudaGetSymbolAddress((void**)&pre,  g_pre);
    cudaGetSymbolAddress((void**)&off,  g_off);
    cudaGetSymbolAddress((void**)&cur,  g_cur);
    cudaGetSymbolAddress((void**)&srow, g_srow);

    int* cnt   = pre;
    int* degr  = pre + N_NODES;
    int* state = pre + 2 * N_NODES;

    const int NT = 256;
    const int gEdge  = N_EDGES / NT;              // 6250 exact
    const int gNode  = (N_NODES + NT - 1) / NT;   // 391
    const int gLayer = (N_NODES + NPB - 1) / NPB; // 1563

    cudaMemsetAsync(pre, 0, (2 * N_NODES + 128) * sizeof(int));
    k_hist<<<gEdge, NT>>>(row, col, cnt, degr);
    k_scan<<<SCAN_NB, NT>>>(cnt, degr, x, emb, off, cur, inv,
                            (__half2*)hsA, state, srow);
    k_scatter<<<gEdge, NT>>>(row, col, cur, srow);

    k_layer<false><<<gLayer, NT>>>(off, srow, hsA, W1, b1, inv,
                                   (__half2*)hsB, nullptr);
    k_layer<false><<<gLayer, NT>>>(off, srow, hsB, W2, b2, inv,
                                   (__half2*)hsA, nullptr);
    k_layer<true> <<<gLayer, NT>>>(off, srow, hsA, W3, b3, inv,
                                   nullptr, hout);
    k_out<<<gNode, NT>>>(hout, Wout, bout, out);
}